// round 12
// baseline (speedup 1.0000x reference)
#include <cuda_runtime.h>
#include <cstdint>

#define TT 512
#define BB 256
#define HH 64
#define GG 256     // 4*H
#define RROWS 2    // batch rows per recurrence CTA -> 128 CTAs
#define PF 8       // gx prefetch depth (steps ahead); keep unroll pragma in sync
#define GXR 32     // batch-time rows per gx CTA
#define KPH 32     // K per smem phase in gx
static_assert(PF == 8, "update '#pragma unroll 8' in lstm_rec_kernel if PF changes");

// Scratch (device globals; no allocation in kernel_launch)
__device__ float g_gx[(size_t)TT * BB * GG];   // [T][B][4H] permuted col order
__device__ float g_hA[(size_t)TT * BB * HH];   // [T][B][H]
__device__ float g_hB[(size_t)TT * BB * HH];

// ---- packed fp32x2 helpers (Blackwell FFMA2 via PTX) ----------------------
__device__ __forceinline__ unsigned long long ffma2(unsigned long long a,
                                                    unsigned long long b,
                                                    unsigned long long c) {
    unsigned long long d;
    asm("fma.rn.f32x2 %0, %1, %2, %3;" : "=l"(d) : "l"(a), "l"(b), "l"(c));
    return d;
}
__device__ __forceinline__ unsigned long long fadd2(unsigned long long a,
                                                    unsigned long long b) {
    unsigned long long d;
    asm("add.rn.f32x2 %0, %1, %2;" : "=l"(d) : "l"(a), "l"(b));
    return d;
}
__device__ __forceinline__ float2 unpack2(unsigned long long v) {
    float2 r;
    asm("mov.b64 {%0, %1}, %2;" : "=f"(r.x), "=f"(r.y) : "l"(v));
    return r;
}
__device__ __forceinline__ unsigned long long pack2(float lo, float hi) {
    unsigned long long d;
    asm("mov.b64 %0, {%1, %2};" : "=l"(d) : "f"(lo), "f"(hi));
    return d;
}
// single-MUFU tanh (sm_75+)
__device__ __forceinline__ float tanh_approx(float x) {
    float y;
    asm("tanh.approx.f32 %0, %1;" : "=f"(y) : "f"(x));
    return y;
}

// gate index permutation: slot q <-> (j = q>>2, g = q&3), torch row = g*64+j
__device__ __forceinline__ int perm_row(int q) { return (q & 3) * 64 + (q >> 2); }

// ---------------------------------------------------------------------------
// Layer 0 input projection (d_in = 2), writes permuted gx layout.
// grid = T, block = 256
// ---------------------------------------------------------------------------
__global__ __launch_bounds__(256) void lstm_gx0_kernel(
    const float* __restrict__ x,      // [B][T][2]
    const float* __restrict__ Wih,    // [256][2]
    const float* __restrict__ bih,
    const float* __restrict__ bhh,
    float* __restrict__ gxout)        // [T][B][256] permuted
{
    __shared__ float xs[2 * BB];
    const int t = blockIdx.x;
    const int tid = threadIdx.x;
    const int wr = perm_row(tid);

    xs[2 * tid]     = x[((size_t)tid * TT + t) * 2 + 0];
    xs[2 * tid + 1] = x[((size_t)tid * TT + t) * 2 + 1];
    const float w0   = Wih[wr * 2];
    const float w1   = Wih[wr * 2 + 1];
    const float bias = bih[wr] + bhh[wr];
    __syncthreads();

    float* op = gxout + (size_t)t * BB * GG + tid;
#pragma unroll 4
    for (int r = 0; r < BB; r++) {
        op[r * GG] = fmaf(xs[2 * r], w0, fmaf(xs[2 * r + 1], w1, bias));
    }
}

// ---------------------------------------------------------------------------
// Layers 1..4 input projection v3: [T*B,64] x [64,256] + bias.
// k-major x in smem as row-pair float2; W k-major in smem.
// Thread tile: 8 rows x 4 gates (acc[gate][rowpair]).
// grid = T*B/32, block = 256.
// ---------------------------------------------------------------------------
__global__ __launch_bounds__(256, 2) void lstm_gx_kernel(
    const float* __restrict__ xseq,   // [T][B][64]
    const float* __restrict__ Wih,    // [256][64]
    const float* __restrict__ bih,
    const float* __restrict__ bhh,
    float* __restrict__ gxout)        // [T][B][256] permuted
{
    __shared__ float Wt[KPH][GG];                       // 32KB [k][slot]
    __shared__ __align__(16) float2 xsT[KPH][18];       // [k][rowpair], padded
    __shared__ float bs[GG];

    const int tid = threadIdx.x;
    const size_t base = (size_t)blockIdx.x * GXR;
    const int gc = tid & 63;          // gate group: slots 4gc..4gc+3
    const int rq = tid >> 6;          // row group: rows 8rq..8rq+7
    const int wr = (tid & 3) * 64 + (tid >> 2);   // torch row of slot tid

    bs[tid] = bih[wr] + bhh[wr];

    unsigned long long acc[4][4];     // [gate][rowpair]
#pragma unroll
    for (int g = 0; g < 4; g++)
#pragma unroll
        for (int rp = 0; rp < 4; rp++) acc[g][rp] = 0ull;

#pragma unroll 1
    for (int ph = 0; ph < 2; ph++) {
        const int k0 = ph * KPH;
        if (ph) __syncthreads();      // all reads of previous phase done
        // W phase load: Wih[wr][k0..k0+31] -> Wt[k][tid]
        {
            const float4* wp = reinterpret_cast<const float4*>(
                Wih + (size_t)wr * HH + k0);
#pragma unroll
            for (int i = 0; i < KPH / 4; i++) {
                float4 v = wp[i];
                Wt[4 * i + 0][tid] = v.x;
                Wt[4 * i + 1][tid] = v.y;
                Wt[4 * i + 2][tid] = v.z;
                Wt[4 * i + 3][tid] = v.w;
            }
        }
        // x transposed phase load: row = tid>>3 (0..31), cols c4=(tid&7)*4
        {
            const int row = tid >> 3, c4 = (tid & 7) * 4;
            const float4 v = *reinterpret_cast<const float4*>(
                xseq + (base + row) * HH + k0 + c4);
            const int rp = row >> 1, comp = row & 1;
            reinterpret_cast<float*>(&xsT[c4 + 0][rp])[comp] = v.x;
            reinterpret_cast<float*>(&xsT[c4 + 1][rp])[comp] = v.y;
            reinterpret_cast<float*>(&xsT[c4 + 2][rp])[comp] = v.z;
            reinterpret_cast<float*>(&xsT[c4 + 3][rp])[comp] = v.w;
        }
        __syncthreads();

#pragma unroll 2
        for (int k = 0; k < KPH; k++) {
            const float4 wq = *reinterpret_cast<const float4*>(&Wt[k][4 * gc]);
            const ulonglong2 xv0 =
                *reinterpret_cast<const ulonglong2*>(&xsT[k][4 * rq]);
            const ulonglong2 xv1 =
                *reinterpret_cast<const ulonglong2*>(&xsT[k][4 * rq + 2]);
            const unsigned long long ws[4] = {
                pack2(wq.x, wq.x), pack2(wq.y, wq.y),
                pack2(wq.z, wq.z), pack2(wq.w, wq.w) };
#pragma unroll
            for (int g = 0; g < 4; g++) {
                acc[g][0] = ffma2(ws[g], xv0.x, acc[g][0]);
                acc[g][1] = ffma2(ws[g], xv0.y, acc[g][1]);
                acc[g][2] = ffma2(ws[g], xv1.x, acc[g][2]);
                acc[g][3] = ffma2(ws[g], xv1.y, acc[g][3]);
            }
        }
    }

    // epilogue: per rowpair, transpose to row-major and STG.128 with bias
    const float4 bv = *reinterpret_cast<const float4*>(&bs[4 * gc]);
#pragma unroll
    for (int rp = 0; rp < 4; rp++) {
        float2 g0 = unpack2(acc[0][rp]);
        float2 g1 = unpack2(acc[1][rp]);
        float2 g2 = unpack2(acc[2][rp]);
        float2 g3 = unpack2(acc[3][rp]);
        float4 lo = make_float4(bv.x + g0.x, bv.y + g1.x, bv.z + g2.x, bv.w + g3.x);
        float4 hi = make_float4(bv.x + g0.y, bv.y + g1.y, bv.z + g2.y, bv.w + g3.y);
        *reinterpret_cast<float4*>(
            &gxout[(base + rq * 8 + 2 * rp + 0) * GG + 4 * gc]) = lo;
        *reinterpret_cast<float4*>(
            &gxout[(base + rq * 8 + 2 * rp + 1) * GG + 4 * gc]) = hi;
    }
}

// ---------------------------------------------------------------------------
// Recurrence v4 (k-split): 256 threads, 2 rows x 4 warps/row.
// Thread = (row r, hidden j, half kap): owns ALL 4 gates of j over HALF the
// k-range (interleaved 16B chunks: kap picks even/odd chunks so the two
// lane-groups' LDS addresses differ by 16B -> bank-conflict-free).
// Per thread/step: 8 LDS.128 (was 16), 64 FFMA2 in 8-deep chains (was 16),
// partner lane l^16 holds the other half -> 2 x 64-bit shfl.xor reduce.
// All 4 gates in-thread: no gate-gather shuffles. c redundant in partners.
// grid = 128, block = 256.
// ---------------------------------------------------------------------------
__global__ __launch_bounds__(256, 1) void lstm_rec_kernel(
    const float* __restrict__ gx,     // [T][B][256] permuted
    const float* __restrict__ Whh,    // [256][64]
    float* __restrict__ hout)         // [T][B][64]
{
    __shared__ __align__(16) float h_s[2][RROWS * HH];
    const int tid = threadIdx.x;
    const int l = tid & 31;
    const int w = tid >> 5;           // warp 0..7
    const int r = w >> 2;             // batch row within CTA
    const int ww = w & 3;             // warp within row
    const int kap = l >> 4;           // k-half (0: even chunks, 1: odd)
    const int j = ww * 16 + (l & 15); // hidden index 0..63
    const int row0 = blockIdx.x * RROWS;
    const int barid = 1 + r;

    // W_hh rows for all 4 gates of j, this thread's 8 interleaved chunks.
    // wg[g][2i] / wg[g][2i+1] = k-pairs of chunk (2i+kap).
    unsigned long long wg[4][16];
#pragma unroll
    for (int g = 0; g < 4; g++) {
        const double2* wp =
            reinterpret_cast<const double2*>(Whh + (size_t)(g * 64 + j) * HH);
#pragma unroll
        for (int i = 0; i < 8; i++) {
            double2 d = wp[2 * i + kap];
            wg[g][2 * i]     = __double_as_longlong(d.x);
            wg[g][2 * i + 1] = __double_as_longlong(d.y);
        }
    }

    // gx pointer: slots 4j..4j+3 (gates i,f,g~,o) as one float4.
    // Partner lanes (l, l^16) load the SAME address -> L1TEX dedups.
    const float4* gxp = reinterpret_cast<const float4*>(
        gx + (size_t)(row0 + r) * GG + 4 * j);

    float c = 0.0f;
    if (tid < RROWS * HH) h_s[0][tid] = 0.0f;
    __syncthreads();

    // prefetch ring: slot i holds gx float4 for step (t : t % PF == i)
    float4 gring[PF];
#pragma unroll
    for (int i = 0; i < PF; i++)
        gring[i] = __ldg(gxp + (size_t)i * (BB * GG / 4));

#pragma unroll 8
    for (int t = 0; t < TT; t++) {
        const int p = t & 1;
        const int slot = t & (PF - 1);
        const float4 gxv = gring[slot];
        if (t + PF < TT)
            gring[slot] = __ldg(gxp + (size_t)(t + PF) * (BB * GG / 4));

        // half-dots: 4 gates x 16 FFMA2 in two 8-deep chains each
        unsigned long long a0 = 0ull, b0 = 0ull, a1 = 0ull, b1 = 0ull;
        unsigned long long a2 = 0ull, b2 = 0ull, a3 = 0ull, b3 = 0ull;
        const double2* hp = reinterpret_cast<const double2*>(h_s[p] + r * HH);
#pragma unroll
        for (int i = 0; i < 8; i++) {
            double2 hv = hp[2 * i + kap];
            const unsigned long long hx = __double_as_longlong(hv.x);
            const unsigned long long hy = __double_as_longlong(hv.y);
            a0 = ffma2(wg[0][2 * i], hx, a0); b0 = ffma2(wg[0][2 * i + 1], hy, b0);
            a1 = ffma2(wg[1][2 * i], hx, a1); b1 = ffma2(wg[1][2 * i + 1], hy, b1);
            a2 = ffma2(wg[2][2 * i], hx, a2); b2 = ffma2(wg[2][2 * i + 1], hy, b2);
            a3 = ffma2(wg[3][2 * i], hx, a3); b3 = ffma2(wg[3][2 * i + 1], hy, b3);
        }
        float2 s0 = unpack2(fadd2(a0, b0));
        float2 s1 = unpack2(fadd2(a1, b1));
        float2 s2 = unpack2(fadd2(a2, b2));
        float2 s3 = unpack2(fadd2(a3, b3));

        // pack partials, exchange with k-partner (lane l^16), sum halves
        unsigned long long p01 = pack2(s0.x + s0.y, s1.x + s1.y);
        unsigned long long p23 = pack2(s2.x + s2.y, s3.x + s3.y);
        const unsigned m = 0xffffffffu;
        unsigned long long q01 = __shfl_xor_sync(m, p01, 16, 32);
        unsigned long long q23 = __shfl_xor_sync(m, p23, 16, 32);
        float2 t01 = unpack2(fadd2(p01, q01));
        float2 t23 = unpack2(fadd2(p23, q23));

        const float vi = gxv.x + t01.x;
        const float vf = gxv.y + t01.y;
        const float vg = gxv.z + t23.x;
        const float vo = gxv.w + t23.y;

        const float ig = fmaf(tanh_approx(vi * 0.5f), 0.5f, 0.5f);
        const float fg = fmaf(tanh_approx(vf * 0.5f), 0.5f, 0.5f);
        const float Gg = tanh_approx(vg);
        const float og = fmaf(tanh_approx(vo * 0.5f), 0.5f, 0.5f);

        c = fmaf(fg, c, ig * Gg);
        const float hv = og * tanh_approx(c);

        if (kap == 0) {
            h_s[p ^ 1][r * HH + j] = hv;
            hout[((size_t)t * BB + row0 + r) * HH + j] = hv;
        }
        // per-row named barrier: this row's 4 warps (128 threads)
        asm volatile("bar.sync %0, %1;" :: "r"(barid), "r"(128) : "memory");
    }
}

// ---------------------------------------------------------------------------
// Final linear head. grid = T, block = 256.
// ---------------------------------------------------------------------------
__global__ __launch_bounds__(256) void lstm_lin_kernel(
    const float* __restrict__ hseq,   // [T][B][64]
    const float* __restrict__ Wl,     // [64]
    const float* __restrict__ bl,     // [1]
    float* __restrict__ out)          // [B][T]
{
    __shared__ float4 wl4[16];
    const int t = blockIdx.x;
    const int b = threadIdx.x;
    if (threadIdx.x < 16)
        wl4[threadIdx.x] = reinterpret_cast<const float4*>(Wl)[threadIdx.x];
    __syncthreads();

    const float4* hp = reinterpret_cast<const float4*>(hseq + ((size_t)t * BB + b) * HH);
    float acc = bl[0];
#pragma unroll
    for (int k4 = 0; k4 < 16; k4++) {
        const float4 h = hp[k4];
        const float4 w = wl4[k4];
        acc = fmaf(h.x, w.x, acc);
        acc = fmaf(h.y, w.y, acc);
        acc = fmaf(h.z, w.z, acc);
        acc = fmaf(h.w, w.w, acc);
    }
    out[(size_t)b * TT + t] = acc;
}

// ---------------------------------------------------------------------------
extern "C" void kernel_launch(void* const* d_in, const int* in_sizes, int n_in,
                              void* d_out, int out_size)
{
    (void)in_sizes; (void)n_in; (void)out_size;

    const float* x = (const float*)d_in[0];
    const float* Wih[5]; const float* Whh[5]; const float* bih[5]; const float* bhh[5];
    for (int l = 0; l < 5; l++) {
        Wih[l] = (const float*)d_in[1 + 4 * l];
        Whh[l] = (const float*)d_in[2 + 4 * l];
        bih[l] = (const float*)d_in[3 + 4 * l];
        bhh[l] = (const float*)d_in[4 + 4 * l];
    }
    const float* Wl = (const float*)d_in[21];
    const float* bl = (const float*)d_in[22];
    float* out = (float*)d_out;

    float *gx, *hA, *hB;
    cudaGetSymbolAddress((void**)&gx, g_gx);
    cudaGetSymbolAddress((void**)&hA, g_hA);
    cudaGetSymbolAddress((void**)&hB, g_hB);
    float* bufs[2] = { hA, hB };

    // layer 0
    lstm_gx0_kernel<<<TT, 256>>>(x, Wih[0], bih[0], bhh[0], gx);
    lstm_rec_kernel<<<BB / RROWS, 256>>>(gx, Whh[0], bufs[0]);

    // layers 1..4
    for (int l = 1; l < 5; l++) {
        const float* hin = bufs[(l - 1) & 1];
        float* ho = bufs[l & 1];
        lstm_gx_kernel<<<(TT * BB) / GXR, 256>>>(hin, Wih[l], bih[l], bhh[l], gx);
        lstm_rec_kernel<<<BB / RROWS, 256>>>(gx, Whh[l], ho);
    }

    // linear head (layer 4 wrote bufs[0])
    lstm_lin_kernel<<<TT, 256>>>(bufs[0], Wl, bl, out);
}

// round 13
// speedup vs baseline: 1.0986x; 1.0986x over previous
#include <cuda_runtime.h>
#include <cstdint>

#define TT 512
#define BB 256
#define HH 64
#define GG 256     // 4*H
#define RROWS 2    // batch rows per recurrence CTA -> 128 CTAs
#define PF 8       // MODE0 gx prefetch depth; keep '#pragma unroll 8' in sync
static_assert(PF == 8, "update '#pragma unroll 8' in lstm_rec_fused if PF changes");

// Scratch (device globals; no allocation in kernel_launch)
__device__ float g_gx[(size_t)TT * BB * GG];   // [T][B][4H] permuted (layer 0 only)
__device__ float g_hA[(size_t)TT * BB * HH];   // [T][B][H]
__device__ float g_hB[(size_t)TT * BB * HH];

// ---- packed fp32x2 helpers (Blackwell FFMA2 via PTX) ----------------------
__device__ __forceinline__ unsigned long long ffma2(unsigned long long a,
                                                    unsigned long long b,
                                                    unsigned long long c) {
    unsigned long long d;
    asm("fma.rn.f32x2 %0, %1, %2, %3;" : "=l"(d) : "l"(a), "l"(b), "l"(c));
    return d;
}
__device__ __forceinline__ unsigned long long fadd2(unsigned long long a,
                                                    unsigned long long b) {
    unsigned long long d;
    asm("add.rn.f32x2 %0, %1, %2;" : "=l"(d) : "l"(a), "l"(b));
    return d;
}
__device__ __forceinline__ float2 unpack2(unsigned long long v) {
    float2 r;
    asm("mov.b64 {%0, %1}, %2;" : "=f"(r.x), "=f"(r.y) : "l"(v));
    return r;
}
__device__ __forceinline__ unsigned long long pack2(float lo, float hi) {
    unsigned long long d;
    asm("mov.b64 %0, {%1, %2};" : "=l"(d) : "f"(lo), "f"(hi));
    return d;
}
// single-MUFU tanh (sm_75+)
__device__ __forceinline__ float tanh_approx(float x) {
    float y;
    asm("tanh.approx.f32 %0, %1;" : "=f"(y) : "f"(x));
    return y;
}
__device__ __forceinline__ float sig_approx(float x) {
    return fmaf(tanh_approx(x * 0.5f), 0.5f, 0.5f);
}

// gate slot permutation: slot q <-> (j = q>>2, g = q&3), torch row = g*64+j
__device__ __forceinline__ int perm_row(int q) { return (q & 3) * 64 + (q >> 2); }

// ---------------------------------------------------------------------------
// Layer 0 input projection (d_in = 2), writes permuted gx layout.
// grid = T, block = 256
// ---------------------------------------------------------------------------
__global__ __launch_bounds__(256) void lstm_gx0_kernel(
    const float* __restrict__ x,      // [B][T][2]
    const float* __restrict__ Wih,    // [256][2]
    const float* __restrict__ bih,
    const float* __restrict__ bhh,
    float* __restrict__ gxout)        // [T][B][256] permuted
{
    __shared__ float xs[2 * BB];
    const int t = blockIdx.x;
    const int tid = threadIdx.x;
    const int wr = perm_row(tid);

    xs[2 * tid]     = x[((size_t)tid * TT + t) * 2 + 0];
    xs[2 * tid + 1] = x[((size_t)tid * TT + t) * 2 + 1];
    const float w0   = Wih[wr * 2];
    const float w1   = Wih[wr * 2 + 1];
    const float bias = bih[wr] + bhh[wr];
    __syncthreads();

    float* op = gxout + (size_t)t * BB * GG + tid;
#pragma unroll 4
    for (int r = 0; r < BB; r++) {
        op[r * GG] = fmaf(xs[2 * r], w0, fmaf(xs[2 * r + 1], w1, bias));
    }
}

// ---------------------------------------------------------------------------
// Fused recurrence. 256 threads, 2 batch rows per CTA, grid = 128.
// Thread = (hidden j, k-quarter kq): owns ALL 4 gates of j over 16 of 64 k,
// for BOTH batch rows (weights stored once per CTA -> fits registers).
//   lane = [kq(2b) | j_low(3b)], warp = j_high  -> kq partners in-warp.
// MODE 0 (layer 0):  gate pre-activation = gx (precomputed) + W_hh.h
//   gx read via 8-deep per-thread float4 register ring (proven R7 pattern).
// MODE 1 (layers 1-4): gate = bias + W_ih.h_prev[t] + W_hh.h[t-1]
//   h_prev staged into a 4-slot smem ring by threads 0..127 via a 4-deep
//   per-thread register pipeline with 6 steps of lead (DRAM fully hidden).
// Reduction over k-quarters: shfl.xor 8 then 16, packed f32x2.
// One __syncthreads per step. Eliminates the separate gx GEMM kernels.
// ---------------------------------------------------------------------------
template <int MODE>
__global__ __launch_bounds__(256, 1) void lstm_rec_fused(
    const float* __restrict__ gx_or_hprev, // MODE0: gx [T][B][256]; MODE1: h_prev [T][B][64]
    const float* __restrict__ Whh,    // [256][64]
    const float* __restrict__ Wih,    // [256][64]  (MODE1)
    const float* __restrict__ bih,    // [256]      (MODE1)
    const float* __restrict__ bhh,    // [256]      (MODE1)
    float* __restrict__ hout)         // [T][B][64]
{
    __shared__ __align__(16) float h_s[2][RROWS * HH];
    __shared__ __align__(16) float ring[4][RROWS * HH];   // MODE1 h_prev ring
    const int tid = threadIdx.x;
    const int l = tid & 31;
    const int w = tid >> 5;           // warp 0..7 = j_high
    const int kq = l >> 3;            // k-quarter 0..3
    const int j = w * 8 + (l & 7);    // hidden index 0..63
    const int row0 = blockIdx.x * RROWS;

    // Weights: per gate g (torch row g*64+j), chunks c = 4*i + kq (i=0..3),
    // chunk = 16B = 2 packed f32x2. whh/wih: [gate][2*i+half] -> 32 u64 each.
    unsigned long long whh[4][8], wih[4][8];
    float bias[4];
#pragma unroll
    for (int g = 0; g < 4; g++) {
        const double2* hp = reinterpret_cast<const double2*>(Whh + (size_t)(g * 64 + j) * HH);
#pragma unroll
        for (int i = 0; i < 4; i++) {
            double2 d = hp[4 * i + kq];
            whh[g][2 * i]     = __double_as_longlong(d.x);
            whh[g][2 * i + 1] = __double_as_longlong(d.y);
        }
        if (MODE == 1) {
            const double2* ip = reinterpret_cast<const double2*>(Wih + (size_t)(g * 64 + j) * HH);
#pragma unroll
            for (int i = 0; i < 4; i++) {
                double2 d = ip[4 * i + kq];
                wih[g][2 * i]     = __double_as_longlong(d.x);
                wih[g][2 * i + 1] = __double_as_longlong(d.y);
            }
            bias[g] = bih[g * 64 + j] + bhh[g * 64 + j];
        } else {
            bias[g] = 0.0f;
        }
    }

    float c0 = 0.0f, c1 = 0.0f;
    if (tid < RROWS * HH) h_s[0][tid] = 0.0f;

    // MODE0: gx register rings (all kq of a j load same float4 -> L1 dedup)
    float4 gr0[PF], gr1[PF];
    const float4* gxp0 = nullptr; const float4* gxp1 = nullptr;
    // MODE1: h_prev loader state (threads 0..127)
    float v[4];
    const float* ldp = nullptr;
    if (MODE == 0) {
        gxp0 = reinterpret_cast<const float4*>(gx_or_hprev + (size_t)row0 * GG + 4 * j);
        gxp1 = reinterpret_cast<const float4*>(gx_or_hprev + (size_t)(row0 + 1) * GG + 4 * j);
#pragma unroll
        for (int i = 0; i < PF; i++) {
            gr0[i] = __ldg(gxp0 + (size_t)i * (BB * GG / 4));
            gr1[i] = __ldg(gxp1 + (size_t)i * (BB * GG / 4));
        }
    } else if (tid < RROWS * HH) {
        const int lrow = tid >> 6, jj = tid & 63;
        ldp = gx_or_hprev + (size_t)(row0 + lrow) * HH + jj;
        ring[0][tid] = __ldg(ldp + (size_t)0 * BB * HH);
        ring[1][tid] = __ldg(ldp + (size_t)1 * BB * HH);
#pragma unroll
        for (int i = 0; i < 4; i++)
            v[i] = __ldg(ldp + (size_t)(2 + i) * BB * HH);
    }
    __syncthreads();

#pragma unroll 8
    for (int t = 0; t < TT; t++) {
        const int p = t & 1;

        float4 gxv0, gxv1;
        if (MODE == 0) {
            const int slot = t & (PF - 1);
            gxv0 = gr0[slot]; gxv1 = gr1[slot];
            if (t + PF < TT) {
                gr0[slot] = __ldg(gxp0 + (size_t)(t + PF) * (BB * GG / 4));
                gr1[slot] = __ldg(gxp1 + (size_t)(t + PF) * (BB * GG / 4));
            }
        } else if (tid < RROWS * HH) {
            // stage step t+2 into its slot; refill reg with step t+6
            ring[(t + 2) & 3][tid] = v[t & 3];
            if (t + 6 < TT)
                v[t & 3] = __ldg(ldp + (size_t)(t + 6) * BB * HH);
        }

        // dots: acc[g][row] over this thread's 4 chunks (8 FFMA2 deep each)
        unsigned long long ah[4][2], ai[4][2];
#pragma unroll
        for (int g = 0; g < 4; g++) {
            ah[g][0] = 0ull; ah[g][1] = 0ull;
            ai[g][0] = 0ull; ai[g][1] = 0ull;
        }
        {
            const ulonglong2* hb0 = reinterpret_cast<const ulonglong2*>(h_s[p]);
            const ulonglong2* hb1 = reinterpret_cast<const ulonglong2*>(h_s[p] + HH);
#pragma unroll
            for (int i = 0; i < 4; i++) {
                const int ch = 4 * i + kq;
                ulonglong2 h0 = hb0[ch];
                ulonglong2 h1 = hb1[ch];
#pragma unroll
                for (int g = 0; g < 4; g++) {
                    ah[g][0] = ffma2(whh[g][2 * i], h0.x, ah[g][0]);
                    ah[g][0] = ffma2(whh[g][2 * i + 1], h0.y, ah[g][0]);
                    ah[g][1] = ffma2(whh[g][2 * i], h1.x, ah[g][1]);
                    ah[g][1] = ffma2(whh[g][2 * i + 1], h1.y, ah[g][1]);
                }
            }
        }
        if (MODE == 1) {
            const ulonglong2* xb0 = reinterpret_cast<const ulonglong2*>(ring[t & 3]);
            const ulonglong2* xb1 = reinterpret_cast<const ulonglong2*>(ring[t & 3] + HH);
#pragma unroll
            for (int i = 0; i < 4; i++) {
                const int ch = 4 * i + kq;
                ulonglong2 x0 = xb0[ch];
                ulonglong2 x1 = xb1[ch];
#pragma unroll
                for (int g = 0; g < 4; g++) {
                    ai[g][0] = ffma2(wih[g][2 * i], x0.x, ai[g][0]);
                    ai[g][0] = ffma2(wih[g][2 * i + 1], x0.y, ai[g][0]);
                    ai[g][1] = ffma2(wih[g][2 * i], x1.x, ai[g][1]);
                    ai[g][1] = ffma2(wih[g][2 * i + 1], x1.y, ai[g][1]);
                }
            }
        }

        // per-thread partials -> packed pairs, reduce over kq (xor 8, xor 16)
        float s[4][2];
#pragma unroll
        for (int g = 0; g < 4; g++) {
#pragma unroll
            for (int r = 0; r < 2; r++) {
                float2 u = unpack2(fadd2(ah[g][r], ai[g][r]));
                s[g][r] = u.x + u.y;
            }
        }
        unsigned long long pr0a = pack2(s[0][0], s[1][0]);  // row0 (i,f)
        unsigned long long pr0b = pack2(s[2][0], s[3][0]);  // row0 (g~,o)
        unsigned long long pr1a = pack2(s[0][1], s[1][1]);
        unsigned long long pr1b = pack2(s[2][1], s[3][1]);
        const unsigned m = 0xffffffffu;
        pr0a = fadd2(pr0a, __shfl_xor_sync(m, pr0a, 8, 32));
        pr0b = fadd2(pr0b, __shfl_xor_sync(m, pr0b, 8, 32));
        pr1a = fadd2(pr1a, __shfl_xor_sync(m, pr1a, 8, 32));
        pr1b = fadd2(pr1b, __shfl_xor_sync(m, pr1b, 8, 32));
        pr0a = fadd2(pr0a, __shfl_xor_sync(m, pr0a, 16, 32));
        pr0b = fadd2(pr0b, __shfl_xor_sync(m, pr0b, 16, 32));
        pr1a = fadd2(pr1a, __shfl_xor_sync(m, pr1a, 16, 32));
        pr1b = fadd2(pr1b, __shfl_xor_sync(m, pr1b, 16, 32));

        float2 r0a = unpack2(pr0a), r0b = unpack2(pr0b);
        float2 r1a = unpack2(pr1a), r1b = unpack2(pr1b);

        float vi0 = r0a.x + bias[0], vf0 = r0a.y + bias[1];
        float vg0 = r0b.x + bias[2], vo0 = r0b.y + bias[3];
        float vi1 = r1a.x + bias[0], vf1 = r1a.y + bias[1];
        float vg1 = r1b.x + bias[2], vo1 = r1b.y + bias[3];
        if (MODE == 0) {
            vi0 += gxv0.x; vf0 += gxv0.y; vg0 += gxv0.z; vo0 += gxv0.w;
            vi1 += gxv1.x; vf1 += gxv1.y; vg1 += gxv1.z; vo1 += gxv1.w;
        }

        const float ig0 = sig_approx(vi0), fg0 = sig_approx(vf0);
        const float Gg0 = tanh_approx(vg0), og0 = sig_approx(vo0);
        const float ig1 = sig_approx(vi1), fg1 = sig_approx(vf1);
        const float Gg1 = tanh_approx(vg1), og1 = sig_approx(vo1);

        c0 = fmaf(fg0, c0, ig0 * Gg0);
        c1 = fmaf(fg1, c1, ig1 * Gg1);
        const float h0 = og0 * tanh_approx(c0);
        const float h1 = og1 * tanh_approx(c1);

        if (kq == 0) {   // one writer per j (lanes 0..7 of each warp)
            h_s[p ^ 1][j]      = h0;
            h_s[p ^ 1][HH + j] = h1;
            hout[((size_t)t * BB + row0) * HH + j]     = h0;
            hout[((size_t)t * BB + row0 + 1) * HH + j] = h1;
        }
        __syncthreads();
    }
}

// ---------------------------------------------------------------------------
// Final linear head. grid = T, block = 256.
// ---------------------------------------------------------------------------
__global__ __launch_bounds__(256) void lstm_lin_kernel(
    const float* __restrict__ hseq,   // [T][B][64]
    const float* __restrict__ Wl,     // [64]
    const float* __restrict__ bl,     // [1]
    float* __restrict__ out)          // [B][T]
{
    __shared__ float4 wl4[16];
    const int t = blockIdx.x;
    const int b = threadIdx.x;
    if (threadIdx.x < 16)
        wl4[threadIdx.x] = reinterpret_cast<const float4*>(Wl)[threadIdx.x];
    __syncthreads();

    const float4* hp = reinterpret_cast<const float4*>(hseq + ((size_t)t * BB + b) * HH);
    float acc = bl[0];
#pragma unroll
    for (int k4 = 0; k4 < 16; k4++) {
        const float4 h = hp[k4];
        const float4 w = wl4[k4];
        acc = fmaf(h.x, w.x, acc);
        acc = fmaf(h.y, w.y, acc);
        acc = fmaf(h.z, w.z, acc);
        acc = fmaf(h.w, w.w, acc);
    }
    out[(size_t)b * TT + t] = acc;
}

// ---------------------------------------------------------------------------
extern "C" void kernel_launch(void* const* d_in, const int* in_sizes, int n_in,
                              void* d_out, int out_size)
{
    (void)in_sizes; (void)n_in; (void)out_size;

    const float* x = (const float*)d_in[0];
    const float* Wih[5]; const float* Whh[5]; const float* bih[5]; const float* bhh[5];
    for (int l = 0; l < 5; l++) {
        Wih[l] = (const float*)d_in[1 + 4 * l];
        Whh[l] = (const float*)d_in[2 + 4 * l];
        bih[l] = (const float*)d_in[3 + 4 * l];
        bhh[l] = (const float*)d_in[4 + 4 * l];
    }
    const float* Wl = (const float*)d_in[21];
    const float* bl = (const float*)d_in[22];
    float* out = (float*)d_out;

    float *gx, *hA, *hB;
    cudaGetSymbolAddress((void**)&gx, g_gx);
    cudaGetSymbolAddress((void**)&hA, g_hA);
    cudaGetSymbolAddress((void**)&hB, g_hB);
    float* bufs[2] = { hA, hB };

    // layer 0: tiny input projection + MODE0 recurrence
    lstm_gx0_kernel<<<TT, 256>>>(x, Wih[0], bih[0], bhh[0], gx);
    lstm_rec_fused<0><<<BB / RROWS, 256>>>(gx, Whh[0], nullptr, nullptr, nullptr, bufs[0]);

    // layers 1..4: fully fused (input GEMM inside the recurrence)
    for (int l = 1; l < 5; l++) {
        const float* hin = bufs[(l - 1) & 1];
        float* ho = bufs[l & 1];
        lstm_rec_fused<1><<<BB / RROWS, 256>>>(hin, Whh[l], Wih[l], bih[l], bhh[l], ho);
    }

    // linear head (layer 4 wrote bufs[0])
    lstm_lin_kernel<<<TT, 256>>>(bufs[0], Wl, bl, out);
}